// round 12
// baseline (speedup 1.0000x reference)
#include <cuda_runtime.h>

#define NMAX 100000
#define EMAX 2000000
#define FSTRIDE 32          // feat/aggF row stride in floats (128B rows; first 20 used)

// Scratch (__device__ globals; zero-initialized at load; every kernel restores
// the zero state of the accumulator it consumes -> graph replays deterministic)
__device__ __align__(128) float g_feat[NMAX * FSTRIDE];  // [x(3), emb(16), 0...]
__device__ __align__(128) float g_aggF[NMAX * FSTRIDE];  // layer-1 agg (zero in/out)
__device__ __align__(128) float g_bufA[NMAX * 32];       // h1 messages for layer 2
__device__ __align__(128) float g_bufB[NMAX * 32];       // layer-2 agg (zero in/out)
__device__ float g_deg[NMAX];                            // weighted degree (zero in/out)
__device__ float g_dinv[NMAX];                           // rsqrt(deg+1)

// ---------------------------------------------------------------------------
// deg[col] += ew, 4 edges per thread (vectorized index/weight loads)
__global__ void deg_kernel(const int* __restrict__ col, const float* __restrict__ ew, int E4) {
    int t = blockIdx.x * blockDim.x + threadIdx.x;
    if (t >= E4) return;
    int4   c4 = ((const int4*)col)[t];
    float4 w4 = ((const float4*)ew)[t];
    atomicAdd(&g_deg[c4.x], w4.x);
    atomicAdd(&g_deg[c4.y], w4.y);
    atomicAdd(&g_deg[c4.z], w4.z);
    atomicAdd(&g_deg[c4.w], w4.w);
}

// ---------------------------------------------------------------------------
// Per-node: dinv = rsqrt(deg+1) (then deg := 0 for next replay);
// emb = relu(c@We1+be1)@We2+be2;  feat = [x, emb, 0...] -> g_feat (stride 32).
__global__ void embed_kernel(const float* __restrict__ x, const float* __restrict__ c,
                             const float* __restrict__ We1, const float* __restrict__ be1,
                             const float* __restrict__ We2, const float* __restrict__ be2,
                             int n) {
    __shared__ float4 sPack[128];   // {We1[0][j], We1[1][j], be1[j], 0}
    __shared__ float4 sWe2[512];    // [128][16] as float4
    __shared__ float  sbe2[16];

    for (int j = threadIdx.x; j < 128; j += blockDim.x)
        sPack[j] = make_float4(We1[j], We1[128 + j], be1[j], 0.f);
    for (int j = threadIdx.x; j < 512; j += blockDim.x)
        sWe2[j] = ((const float4*)We2)[j];
    if (threadIdx.x < 16) sbe2[threadIdx.x] = be2[threadIdx.x];
    __syncthreads();

    int i = blockIdx.x * blockDim.x + threadIdx.x;
    if (i >= n) return;

    g_dinv[i] = rsqrtf(g_deg[i] + 1.0f);   // self-loop weight 1 folded in
    g_deg[i]  = 0.0f;                      // restore zero state

    float c0 = c[2 * i], c1 = c[2 * i + 1];
    float emb[16];
#pragma unroll
    for (int k = 0; k < 16; k++) emb[k] = sbe2[k];

#pragma unroll 4
    for (int j = 0; j < 128; j++) {
        float4 p = sPack[j];
        float h = fmaxf(fmaf(c0, p.x, fmaf(c1, p.y, p.z)), 0.f);
#pragma unroll
        for (int q = 0; q < 4; q++) {
            float4 w = sWe2[j * 4 + q];
            emb[4 * q + 0] = fmaf(h, w.x, emb[4 * q + 0]);
            emb[4 * q + 1] = fmaf(h, w.y, emb[4 * q + 1]);
            emb[4 * q + 2] = fmaf(h, w.z, emb[4 * q + 2]);
            emb[4 * q + 3] = fmaf(h, w.w, emb[4 * q + 3]);
        }
    }

    float4* fp = (float4*)&g_feat[(size_t)i * FSTRIDE];
    fp[0] = make_float4(x[3 * i], x[3 * i + 1], x[3 * i + 2], emb[0]);
    fp[1] = make_float4(emb[1],  emb[2],  emb[3],  emb[4]);
    fp[2] = make_float4(emb[5],  emb[6],  emb[7],  emb[8]);
    fp[3] = make_float4(emb[9],  emb[10], emb[11], emb[12]);
    fp[4] = make_float4(emb[13], emb[14], emb[15], 0.f);
}

// ---------------------------------------------------------------------------
// Scatter layer 1: 5 threads per edge (all lanes active), rows 128B-aligned
// (stride 32 floats, first 5 float4 used) -> one L1 line per gather and RED.
// aggF[col] += nrm * feat[row], nrm = dinv[r]*ew*dinv[c]
__global__ void scatter1_kernel(const int* __restrict__ ei, const float* __restrict__ ew, int E) {
    int t = blockIdx.x * blockDim.x + threadIdx.x;
    int e = t / 5;
    int q = t - e * 5;
    if (e >= E) return;
    int r = ei[e];
    int c = ei[E + e];
    float nrm = g_dinv[r] * ew[e] * g_dinv[c];
    float4 v = ((const float4*)g_feat)[(size_t)r * 8 + q];
    float vx = v.x * nrm, vy = v.y * nrm, vz = v.z * nrm, vw = v.w * nrm;
    float4* dst = ((float4*)g_aggF) + (size_t)c * 8 + q;
    asm volatile("red.global.add.v4.f32 [%0], {%1,%2,%3,%4};"
                 :: "l"(dst), "f"(vx), "f"(vy), "f"(vz), "f"(vw)
                 : "memory");
}

// ---------------------------------------------------------------------------
// Mid (streaming t@W1 only): t = aggF + dinv^2*feat_self, consumed 4-at-a-time.
// h1 = relu(t@W1 + b1) -> bufA. Restores aggF zeros, pre-zeroes bufB.
// TB=128 for more blocks -> latency hiding at small grid.
__global__ void __launch_bounds__(128)
mid_kernel(const float* __restrict__ W1, const float* __restrict__ b1, int n) {
    __shared__ float4 sW1[152];  // [19][32] as float4
    __shared__ float  sb1[32];
    for (int j = threadIdx.x; j < 152; j += blockDim.x) sW1[j] = ((const float4*)W1)[j];
    if (threadIdx.x < 32) sb1[threadIdx.x] = b1[threadIdx.x];
    __syncthreads();

    int i = blockIdx.x * blockDim.x + threadIdx.x;
    if (i >= n) return;

    float d = g_dinv[i];
    float s = d * d;
    float4*       aggp = (float4*)&g_aggF[(size_t)i * FSTRIDE];
    const float4* fp   = (const float4*)&g_feat[(size_t)i * FSTRIDE];

    float4 acc[8];
#pragma unroll
    for (int q = 0; q < 8; q++)
        acc[q] = make_float4(sb1[4*q], sb1[4*q+1], sb1[4*q+2], sb1[4*q+3]);

#pragma unroll
    for (int c4 = 0; c4 < 5; c4++) {
        float4 a = aggp[c4];
        float4 f = fp[c4];
        aggp[c4] = make_float4(0.f, 0.f, 0.f, 0.f);   // restore zeros
        float tv[4] = { fmaf(s, f.x, a.x), fmaf(s, f.y, a.y),
                        fmaf(s, f.z, a.z), fmaf(s, f.w, a.w) };
#pragma unroll
        for (int j = 0; j < 4; j++) {
            int r = c4 * 4 + j;
            if (r < 19) {
                float t = tv[j];
#pragma unroll
                for (int q = 0; q < 8; q++) {
                    float4 w = sW1[r * 8 + q];
                    acc[q].x = fmaf(t, w.x, acc[q].x);
                    acc[q].y = fmaf(t, w.y, acc[q].y);
                    acc[q].z = fmaf(t, w.z, acc[q].z);
                    acc[q].w = fmaf(t, w.w, acc[q].w);
                }
            }
        }
    }

    float4* outp = (float4*)&g_bufA[(size_t)i * 32];
    float4* zp   = (float4*)&g_bufB[(size_t)i * 32];
#pragma unroll
    for (int q = 0; q < 8; q++) {
        outp[q] = make_float4(fmaxf(acc[q].x, 0.f), fmaxf(acc[q].y, 0.f),
                              fmaxf(acc[q].z, 0.f), fmaxf(acc[q].w, 0.f));
        zp[q]   = make_float4(0.f, 0.f, 0.f, 0.f);   // pre-zero layer-2 agg
    }
}

// ---------------------------------------------------------------------------
// Scatter layer 2: 8 threads per edge over 32-wide h1 (RED lane floor;
// rows are naturally 128B-aligned -> one line per edge already).
__global__ void scatter2_kernel(const int* __restrict__ ei, const float* __restrict__ ew, int E) {
    int t = blockIdx.x * blockDim.x + threadIdx.x;
    int e = t >> 3;
    int q = t & 7;
    if (e >= E) return;
    int r = ei[e];
    int c = ei[E + e];
    float nrm = g_dinv[r] * ew[e] * g_dinv[c];
    float4 v = ((const float4*)g_bufA)[(size_t)r * 8 + q];
    float vx = v.x * nrm, vy = v.y * nrm, vz = v.z * nrm, vw = v.w * nrm;
    float4* dst = ((float4*)g_bufB) + (size_t)c * 8 + q;
    asm volatile("red.global.add.v4.f32 [%0], {%1,%2,%3,%4};"
                 :: "l"(dst), "f"(vx), "f"(vy), "f"(vz), "f"(vw)
                 : "memory");
}

// ---------------------------------------------------------------------------
// Final (streaming W2 post-aggregation): u = aggB + dinv^2*h1_self;
// h2 = relu(u@W2 + b2); out = h2 @ Wfc + bfc. Restores bufB zeros. TB=128.
__global__ void __launch_bounds__(128)
final_kernel(const float* __restrict__ W2, const float* __restrict__ b2,
             const float* __restrict__ Wfc, const float* __restrict__ bfc,
             float* __restrict__ out, int n) {
    __shared__ float4 sW2[256];  // [32][32] as float4
    __shared__ float  sb2[32];
    __shared__ float  sWfc[32];
    __shared__ float  sbfc;
    for (int j = threadIdx.x; j < 256; j += blockDim.x) sW2[j] = ((const float4*)W2)[j];
    if (threadIdx.x < 32) { sb2[threadIdx.x] = b2[threadIdx.x]; sWfc[threadIdx.x] = Wfc[threadIdx.x]; }
    if (threadIdx.x == 0) sbfc = bfc[0];
    __syncthreads();

    int i = blockIdx.x * blockDim.x + threadIdx.x;
    if (i >= n) return;

    float d = g_dinv[i];
    float s = d * d;
    float4*       aggp = (float4*)&g_bufB[(size_t)i * 32];
    const float4* hp   = (const float4*)&g_bufA[(size_t)i * 32];

    float4 acc[8];
#pragma unroll
    for (int q = 0; q < 8; q++)
        acc[q] = make_float4(sb2[4*q], sb2[4*q+1], sb2[4*q+2], sb2[4*q+3]);

#pragma unroll
    for (int c4 = 0; c4 < 8; c4++) {
        float4 a = aggp[c4];
        float4 h = hp[c4];
        aggp[c4] = make_float4(0.f, 0.f, 0.f, 0.f);   // restore zeros
        float uv[4] = { fmaf(s, h.x, a.x), fmaf(s, h.y, a.y),
                        fmaf(s, h.z, a.z), fmaf(s, h.w, a.w) };
#pragma unroll
        for (int j = 0; j < 4; j++) {
            int m = c4 * 4 + j;
            float u = uv[j];
#pragma unroll
            for (int q = 0; q < 8; q++) {
                float4 w = sW2[m * 8 + q];
                acc[q].x = fmaf(u, w.x, acc[q].x);
                acc[q].y = fmaf(u, w.y, acc[q].y);
                acc[q].z = fmaf(u, w.z, acc[q].z);
                acc[q].w = fmaf(u, w.w, acc[q].w);
            }
        }
    }

    float o = sbfc;
#pragma unroll
    for (int q = 0; q < 8; q++) {
        o = fmaf(fmaxf(acc[q].x, 0.f), sWfc[4*q+0], o);
        o = fmaf(fmaxf(acc[q].y, 0.f), sWfc[4*q+1], o);
        o = fmaf(fmaxf(acc[q].z, 0.f), sWfc[4*q+2], o);
        o = fmaf(fmaxf(acc[q].w, 0.f), sWfc[4*q+3], o);
    }
    out[i] = o;
}

// ---------------------------------------------------------------------------
extern "C" void kernel_launch(void* const* d_in, const int* in_sizes, int n_in,
                              void* d_out, int out_size) {
    const float* x   = (const float*)d_in[0];
    const float* c   = (const float*)d_in[1];
    const int*   ei  = (const int*)d_in[2];
    const float* ew  = (const float*)d_in[3];
    const float* We1 = (const float*)d_in[4];
    const float* be1 = (const float*)d_in[5];
    const float* We2 = (const float*)d_in[6];
    const float* be2 = (const float*)d_in[7];
    const float* W1  = (const float*)d_in[8];
    const float* b1  = (const float*)d_in[9];
    const float* W2  = (const float*)d_in[10];
    const float* b2  = (const float*)d_in[11];
    const float* Wfc = (const float*)d_in[12];
    const float* bfc = (const float*)d_in[13];

    int n = in_sizes[1] / 2;   // c is [N, 2]
    int E = in_sizes[3];       // ew is [E]
    const int TB = 256;

    int E4 = E / 4;
    deg_kernel  <<<(E4 + TB - 1) / TB, TB>>>(ei + E, ew, E4);
    embed_kernel<<<(n + TB - 1) / TB, TB>>>(x, c, We1, be1, We2, be2, n);
    scatter1_kernel<<<((size_t)E * 5 + TB - 1) / TB, TB>>>(ei, ew, E);   // aligned, t/5
    mid_kernel  <<<(n + 127) / 128, 128>>>(W1, b1, n);
    scatter2_kernel<<<((size_t)E * 8 + TB - 1) / TB, TB>>>(ei, ew, E);
    final_kernel<<<(n + 127) / 128, 128>>>(W2, b2, Wfc, bfc, (float*)d_out, n);
}

// round 13
// speedup vs baseline: 1.0017x; 1.0017x over previous
#include <cuda_runtime.h>

#define NMAX 100000
#define EMAX 2000000
#define FSTRIDE 32          // feat/aggF row stride in floats (128B rows; first 20 used)

// Scratch (__device__ globals; zero-initialized at load; every kernel restores
// the zero state of the accumulator it consumes -> graph replays deterministic)
__device__ __align__(128) float g_feat[NMAX * FSTRIDE];  // [x(3), emb(16), 0...]
__device__ __align__(128) float g_aggF[NMAX * FSTRIDE];  // layer-1 agg (zero in/out)
__device__ __align__(128) float g_bufA[NMAX * 32];       // h1 messages for layer 2
__device__ __align__(128) float g_bufB[NMAX * 32];       // layer-2 agg (zero in/out)
__device__ float g_deg[NMAX];                            // weighted degree (zero in/out)
__device__ float g_dinv[NMAX];                           // rsqrt(deg+1)

// ---------------------------------------------------------------------------
// deg[col] += ew, 4 edges per thread (vectorized index/weight loads)
__global__ void deg_kernel(const int* __restrict__ col, const float* __restrict__ ew, int E4) {
    int t = blockIdx.x * blockDim.x + threadIdx.x;
    if (t >= E4) return;
    int4   c4 = ((const int4*)col)[t];
    float4 w4 = ((const float4*)ew)[t];
    atomicAdd(&g_deg[c4.x], w4.x);
    atomicAdd(&g_deg[c4.y], w4.y);
    atomicAdd(&g_deg[c4.z], w4.z);
    atomicAdd(&g_deg[c4.w], w4.w);
}

// ---------------------------------------------------------------------------
// Per-node: dinv = rsqrt(deg+1) (then deg := 0 for next replay);
// emb = relu(c@We1+be1)@We2+be2;  feat = [x, emb, 0...] -> g_feat (stride 32).
__global__ void embed_kernel(const float* __restrict__ x, const float* __restrict__ c,
                             const float* __restrict__ We1, const float* __restrict__ be1,
                             const float* __restrict__ We2, const float* __restrict__ be2,
                             int n) {
    __shared__ float4 sPack[128];   // {We1[0][j], We1[1][j], be1[j], 0}
    __shared__ float4 sWe2[512];    // [128][16] as float4
    __shared__ float  sbe2[16];

    for (int j = threadIdx.x; j < 128; j += blockDim.x)
        sPack[j] = make_float4(We1[j], We1[128 + j], be1[j], 0.f);
    for (int j = threadIdx.x; j < 512; j += blockDim.x)
        sWe2[j] = ((const float4*)We2)[j];
    if (threadIdx.x < 16) sbe2[threadIdx.x] = be2[threadIdx.x];
    __syncthreads();

    int i = blockIdx.x * blockDim.x + threadIdx.x;
    if (i >= n) return;

    g_dinv[i] = rsqrtf(g_deg[i] + 1.0f);   // self-loop weight 1 folded in
    g_deg[i]  = 0.0f;                      // restore zero state

    float c0 = c[2 * i], c1 = c[2 * i + 1];
    float emb[16];
#pragma unroll
    for (int k = 0; k < 16; k++) emb[k] = sbe2[k];

#pragma unroll 4
    for (int j = 0; j < 128; j++) {
        float4 p = sPack[j];
        float h = fmaxf(fmaf(c0, p.x, fmaf(c1, p.y, p.z)), 0.f);
#pragma unroll
        for (int q = 0; q < 4; q++) {
            float4 w = sWe2[j * 4 + q];
            emb[4 * q + 0] = fmaf(h, w.x, emb[4 * q + 0]);
            emb[4 * q + 1] = fmaf(h, w.y, emb[4 * q + 1]);
            emb[4 * q + 2] = fmaf(h, w.z, emb[4 * q + 2]);
            emb[4 * q + 3] = fmaf(h, w.w, emb[4 * q + 3]);
        }
    }

    float4* fp = (float4*)&g_feat[(size_t)i * FSTRIDE];
    fp[0] = make_float4(x[3 * i], x[3 * i + 1], x[3 * i + 2], emb[0]);
    fp[1] = make_float4(emb[1],  emb[2],  emb[3],  emb[4]);
    fp[2] = make_float4(emb[5],  emb[6],  emb[7],  emb[8]);
    fp[3] = make_float4(emb[9],  emb[10], emb[11], emb[12]);
    fp[4] = make_float4(emb[13], emb[14], emb[15], 0.f);
}

// ---------------------------------------------------------------------------
// Scatter layer 1: 5 threads per edge (all lanes active), rows 128B-aligned
// (stride 32 floats, first 5 float4 used) -> one L1 line per gather and RED.
// aggF[col] += nrm * feat[row], nrm = dinv[r]*ew*dinv[c]
__global__ void scatter1_kernel(const int* __restrict__ ei, const float* __restrict__ ew, int E) {
    int t = blockIdx.x * blockDim.x + threadIdx.x;
    int e = t / 5;
    int q = t - e * 5;
    if (e >= E) return;
    int r = ei[e];
    int c = ei[E + e];
    float nrm = g_dinv[r] * ew[e] * g_dinv[c];
    float4 v = ((const float4*)g_feat)[(size_t)r * 8 + q];
    float vx = v.x * nrm, vy = v.y * nrm, vz = v.z * nrm, vw = v.w * nrm;
    float4* dst = ((float4*)g_aggF) + (size_t)c * 8 + q;
    asm volatile("red.global.add.v4.f32 [%0], {%1,%2,%3,%4};"
                 :: "l"(dst), "f"(vx), "f"(vy), "f"(vz), "f"(vw)
                 : "memory");
}

// ---------------------------------------------------------------------------
// Mid (streaming t@W1 only): t = aggF + dinv^2*feat_self, consumed 4-at-a-time.
// h1 = relu(t@W1 + b1) -> bufA. Restores aggF zeros, pre-zeroes bufB.
// TB=128 for more blocks -> latency hiding at small grid.
__global__ void __launch_bounds__(128)
mid_kernel(const float* __restrict__ W1, const float* __restrict__ b1, int n) {
    __shared__ float4 sW1[152];  // [19][32] as float4
    __shared__ float  sb1[32];
    for (int j = threadIdx.x; j < 152; j += blockDim.x) sW1[j] = ((const float4*)W1)[j];
    if (threadIdx.x < 32) sb1[threadIdx.x] = b1[threadIdx.x];
    __syncthreads();

    int i = blockIdx.x * blockDim.x + threadIdx.x;
    if (i >= n) return;

    float d = g_dinv[i];
    float s = d * d;
    float4*       aggp = (float4*)&g_aggF[(size_t)i * FSTRIDE];
    const float4* fp   = (const float4*)&g_feat[(size_t)i * FSTRIDE];

    float4 acc[8];
#pragma unroll
    for (int q = 0; q < 8; q++)
        acc[q] = make_float4(sb1[4*q], sb1[4*q+1], sb1[4*q+2], sb1[4*q+3]);

#pragma unroll
    for (int c4 = 0; c4 < 5; c4++) {
        float4 a = aggp[c4];
        float4 f = fp[c4];
        aggp[c4] = make_float4(0.f, 0.f, 0.f, 0.f);   // restore zeros
        float tv[4] = { fmaf(s, f.x, a.x), fmaf(s, f.y, a.y),
                        fmaf(s, f.z, a.z), fmaf(s, f.w, a.w) };
#pragma unroll
        for (int j = 0; j < 4; j++) {
            int r = c4 * 4 + j;
            if (r < 19) {
                float t = tv[j];
#pragma unroll
                for (int q = 0; q < 8; q++) {
                    float4 w = sW1[r * 8 + q];
                    acc[q].x = fmaf(t, w.x, acc[q].x);
                    acc[q].y = fmaf(t, w.y, acc[q].y);
                    acc[q].z = fmaf(t, w.z, acc[q].z);
                    acc[q].w = fmaf(t, w.w, acc[q].w);
                }
            }
        }
    }

    float4* outp = (float4*)&g_bufA[(size_t)i * 32];
    float4* zp   = (float4*)&g_bufB[(size_t)i * 32];
#pragma unroll
    for (int q = 0; q < 8; q++) {
        outp[q] = make_float4(fmaxf(acc[q].x, 0.f), fmaxf(acc[q].y, 0.f),
                              fmaxf(acc[q].z, 0.f), fmaxf(acc[q].w, 0.f));
        zp[q]   = make_float4(0.f, 0.f, 0.f, 0.f);   // pre-zero layer-2 agg
    }
}

// ---------------------------------------------------------------------------
// Scatter layer 2: 8 threads per edge over 32-wide h1 (RED lane floor;
// rows are naturally 128B-aligned -> one line per edge already).
__global__ void scatter2_kernel(const int* __restrict__ ei, const float* __restrict__ ew, int E) {
    int t = blockIdx.x * blockDim.x + threadIdx.x;
    int e = t >> 3;
    int q = t & 7;
    if (e >= E) return;
    int r = ei[e];
    int c = ei[E + e];
    float nrm = g_dinv[r] * ew[e] * g_dinv[c];
    float4 v = ((const float4*)g_bufA)[(size_t)r * 8 + q];
    float vx = v.x * nrm, vy = v.y * nrm, vz = v.z * nrm, vw = v.w * nrm;
    float4* dst = ((float4*)g_bufB) + (size_t)c * 8 + q;
    asm volatile("red.global.add.v4.f32 [%0], {%1,%2,%3,%4};"
                 :: "l"(dst), "f"(vx), "f"(vy), "f"(vz), "f"(vw)
                 : "memory");
}

// ---------------------------------------------------------------------------
// Final (streaming W2 post-aggregation): u = aggB + dinv^2*h1_self;
// h2 = relu(u@W2 + b2); out = h2 @ Wfc + bfc. Restores bufB zeros. TB=128.
__global__ void __launch_bounds__(128)
final_kernel(const float* __restrict__ W2, const float* __restrict__ b2,
             const float* __restrict__ Wfc, const float* __restrict__ bfc,
             float* __restrict__ out, int n) {
    __shared__ float4 sW2[256];  // [32][32] as float4
    __shared__ float  sb2[32];
    __shared__ float  sWfc[32];
    __shared__ float  sbfc;
    for (int j = threadIdx.x; j < 256; j += blockDim.x) sW2[j] = ((const float4*)W2)[j];
    if (threadIdx.x < 32) { sb2[threadIdx.x] = b2[threadIdx.x]; sWfc[threadIdx.x] = Wfc[threadIdx.x]; }
    if (threadIdx.x == 0) sbfc = bfc[0];
    __syncthreads();

    int i = blockIdx.x * blockDim.x + threadIdx.x;
    if (i >= n) return;

    float d = g_dinv[i];
    float s = d * d;
    float4*       aggp = (float4*)&g_bufB[(size_t)i * 32];
    const float4* hp   = (const float4*)&g_bufA[(size_t)i * 32];

    float4 acc[8];
#pragma unroll
    for (int q = 0; q < 8; q++)
        acc[q] = make_float4(sb2[4*q], sb2[4*q+1], sb2[4*q+2], sb2[4*q+3]);

#pragma unroll
    for (int c4 = 0; c4 < 8; c4++) {
        float4 a = aggp[c4];
        float4 h = hp[c4];
        aggp[c4] = make_float4(0.f, 0.f, 0.f, 0.f);   // restore zeros
        float uv[4] = { fmaf(s, h.x, a.x), fmaf(s, h.y, a.y),
                        fmaf(s, h.z, a.z), fmaf(s, h.w, a.w) };
#pragma unroll
        for (int j = 0; j < 4; j++) {
            int m = c4 * 4 + j;
            float u = uv[j];
#pragma unroll
            for (int q = 0; q < 8; q++) {
                float4 w = sW2[m * 8 + q];
                acc[q].x = fmaf(u, w.x, acc[q].x);
                acc[q].y = fmaf(u, w.y, acc[q].y);
                acc[q].z = fmaf(u, w.z, acc[q].z);
                acc[q].w = fmaf(u, w.w, acc[q].w);
            }
        }
    }

    float o = sbfc;
#pragma unroll
    for (int q = 0; q < 8; q++) {
        o = fmaf(fmaxf(acc[q].x, 0.f), sWfc[4*q+0], o);
        o = fmaf(fmaxf(acc[q].y, 0.f), sWfc[4*q+1], o);
        o = fmaf(fmaxf(acc[q].z, 0.f), sWfc[4*q+2], o);
        o = fmaf(fmaxf(acc[q].w, 0.f), sWfc[4*q+3], o);
    }
    out[i] = o;
}

// ---------------------------------------------------------------------------
extern "C" void kernel_launch(void* const* d_in, const int* in_sizes, int n_in,
                              void* d_out, int out_size) {
    const float* x   = (const float*)d_in[0];
    const float* c   = (const float*)d_in[1];
    const int*   ei  = (const int*)d_in[2];
    const float* ew  = (const float*)d_in[3];
    const float* We1 = (const float*)d_in[4];
    const float* be1 = (const float*)d_in[5];
    const float* We2 = (const float*)d_in[6];
    const float* be2 = (const float*)d_in[7];
    const float* W1  = (const float*)d_in[8];
    const float* b1  = (const float*)d_in[9];
    const float* W2  = (const float*)d_in[10];
    const float* b2  = (const float*)d_in[11];
    const float* Wfc = (const float*)d_in[12];
    const float* bfc = (const float*)d_in[13];

    int n = in_sizes[1] / 2;   // c is [N, 2]
    int E = in_sizes[3];       // ew is [E]
    const int TB = 256;

    int E4 = E / 4;
    deg_kernel  <<<(E4 + TB - 1) / TB, TB>>>(ei + E, ew, E4);
    embed_kernel<<<(n + TB - 1) / TB, TB>>>(x, c, We1, be1, We2, be2, n);
    scatter1_kernel<<<((size_t)E * 5 + TB - 1) / TB, TB>>>(ei, ew, E);   // aligned, t/5
    mid_kernel  <<<(n + 127) / 128, 128>>>(W1, b1, n);
    scatter2_kernel<<<((size_t)E * 8 + TB - 1) / TB, TB>>>(ei, ew, E);
    final_kernel<<<(n + 127) / 128, 128>>>(W2, b2, Wfc, bfc, (float*)d_out, n);
}

// round 14
// speedup vs baseline: 1.0241x; 1.0224x over previous
#include <cuda_runtime.h>

#define NMAX 100000
#define EMAX 2000000
#define FPAD 20            // feat width 19 padded to 20 (5 float4), dense rows

// Scratch (__device__ globals; zero-initialized at load; every kernel restores
// the zero state of the accumulator it consumes -> graph replays deterministic)
__device__ __align__(128) float g_feat[NMAX * FPAD];  // [x(3), emb(16), 0]
__device__ __align__(128) float g_aggF[NMAX * FPAD];  // layer-1 agg (zero in/out)
__device__ __align__(128) float g_bufA[NMAX * 32];    // h1 messages for layer 2
__device__ __align__(128) float g_bufB[NMAX * 32];    // layer-2 agg (zero in/out)
__device__ float g_deg[NMAX];                         // weighted degree (zero in/out)
__device__ float g_dinv[NMAX];                        // rsqrt(deg+1)

// ---------------------------------------------------------------------------
// deg[col] += ew, 4 edges per thread (vectorized index/weight loads)
__global__ void deg_kernel(const int* __restrict__ col, const float* __restrict__ ew, int E4) {
    int t = blockIdx.x * blockDim.x + threadIdx.x;
    if (t >= E4) return;
    int4   c4 = ((const int4*)col)[t];
    float4 w4 = ((const float4*)ew)[t];
    atomicAdd(&g_deg[c4.x], w4.x);
    atomicAdd(&g_deg[c4.y], w4.y);
    atomicAdd(&g_deg[c4.z], w4.z);
    atomicAdd(&g_deg[c4.w], w4.w);
}

// ---------------------------------------------------------------------------
// Per-node: dinv = rsqrt(deg+1) (then deg := 0); emb = relu(c@We1+be1)@We2+be2;
// feat = [x, emb, 0] -> g_feat.
__global__ void embed_kernel(const float* __restrict__ x, const float* __restrict__ c,
                             const float* __restrict__ We1, const float* __restrict__ be1,
                             const float* __restrict__ We2, const float* __restrict__ be2,
                             int n) {
    __shared__ float4 sPack[128];   // {We1[0][j], We1[1][j], be1[j], 0}
    __shared__ float4 sWe2[512];    // [128][16] as float4
    __shared__ float  sbe2[16];

    for (int j = threadIdx.x; j < 128; j += blockDim.x)
        sPack[j] = make_float4(We1[j], We1[128 + j], be1[j], 0.f);
    for (int j = threadIdx.x; j < 512; j += blockDim.x)
        sWe2[j] = ((const float4*)We2)[j];
    if (threadIdx.x < 16) sbe2[threadIdx.x] = be2[threadIdx.x];
    __syncthreads();

    int i = blockIdx.x * blockDim.x + threadIdx.x;
    if (i >= n) return;

    g_dinv[i] = rsqrtf(g_deg[i] + 1.0f);   // self-loop weight 1 folded in
    g_deg[i]  = 0.0f;                      // restore zero state

    float c0 = c[2 * i], c1 = c[2 * i + 1];
    float emb[16];
#pragma unroll
    for (int k = 0; k < 16; k++) emb[k] = sbe2[k];

#pragma unroll 4
    for (int j = 0; j < 128; j++) {
        float4 p = sPack[j];
        float h = fmaxf(fmaf(c0, p.x, fmaf(c1, p.y, p.z)), 0.f);
#pragma unroll
        for (int q = 0; q < 4; q++) {
            float4 w = sWe2[j * 4 + q];
            emb[4 * q + 0] = fmaf(h, w.x, emb[4 * q + 0]);
            emb[4 * q + 1] = fmaf(h, w.y, emb[4 * q + 1]);
            emb[4 * q + 2] = fmaf(h, w.z, emb[4 * q + 2]);
            emb[4 * q + 3] = fmaf(h, w.w, emb[4 * q + 3]);
        }
    }

    float4* fp = (float4*)&g_feat[(size_t)i * FPAD];
    fp[0] = make_float4(x[3 * i], x[3 * i + 1], x[3 * i + 2], emb[0]);
    fp[1] = make_float4(emb[1],  emb[2],  emb[3],  emb[4]);
    fp[2] = make_float4(emb[5],  emb[6],  emb[7],  emb[8]);
    fp[3] = make_float4(emb[9],  emb[10], emb[11], emb[12]);
    fp[4] = make_float4(emb[13], emb[14], emb[15], 0.f);
}

// ---------------------------------------------------------------------------
// Scatter layer 1: 5 threads per edge over dense 20-wide feat rows (R7/R11-proven).
__global__ void scatter1_kernel(const int* __restrict__ ei, const float* __restrict__ ew, int E) {
    int t = blockIdx.x * blockDim.x + threadIdx.x;
    int e = t / 5;
    int q = t - e * 5;
    if (e >= E) return;
    int r = ei[e];
    int c = ei[E + e];
    float nrm = g_dinv[r] * ew[e] * g_dinv[c];
    float4 v = ((const float4*)g_feat)[(size_t)r * 5 + q];
    float vx = v.x * nrm, vy = v.y * nrm, vz = v.z * nrm, vw = v.w * nrm;
    float4* dst = ((float4*)g_aggF) + (size_t)c * 5 + q;
    asm volatile("red.global.add.v4.f32 [%0], {%1,%2,%3,%4};"
                 :: "l"(dst), "f"(vx), "f"(vy), "f"(vz), "f"(vw)
                 : "memory");
}

// ---------------------------------------------------------------------------
// Mid, 4 threads per node (thread q -> h1 outputs 8q..8q+7):
// t = aggF + dinv^2*feat_self; h1 = relu(t@W1 + b1) -> bufA.
// Zero-restore of aggF happens AFTER __syncwarp so all group reads complete.
__global__ void mid_kernel(const float* __restrict__ W1, const float* __restrict__ b1, int n) {
    __shared__ float4 sW1[152];  // [19][32] as float4
    __shared__ float4 sb1[8];    // [32] as float4
    for (int j = threadIdx.x; j < 152; j += blockDim.x) sW1[j] = ((const float4*)W1)[j];
    if (threadIdx.x < 8) sb1[threadIdx.x] = ((const float4*)b1)[threadIdx.x];
    __syncthreads();

    int t = blockIdx.x * blockDim.x + threadIdx.x;
    int i = t >> 2;
    int q = t & 3;
    bool valid = (i < n);
    unsigned mask = __ballot_sync(0xffffffffu, valid);
    if (!valid) return;

    float d = g_dinv[i];
    float s = d * d;
    float4*       aggp = (float4*)&g_aggF[(size_t)i * FPAD];
    const float4* fp   = (const float4*)&g_feat[(size_t)i * FPAD];

    float4 acc0 = sb1[2 * q];
    float4 acc1 = sb1[2 * q + 1];

#pragma unroll
    for (int c4 = 0; c4 < 5; c4++) {
        float4 a = aggp[c4];
        float4 f = fp[c4];
        float tv[4] = { fmaf(s, f.x, a.x), fmaf(s, f.y, a.y),
                        fmaf(s, f.z, a.z), fmaf(s, f.w, a.w) };
#pragma unroll
        for (int j = 0; j < 4; j++) {
            int r = c4 * 4 + j;
            if (r < 19) {
                float tt = tv[j];
                float4 w0 = sW1[r * 8 + 2 * q];
                float4 w1 = sW1[r * 8 + 2 * q + 1];
                acc0.x = fmaf(tt, w0.x, acc0.x);
                acc0.y = fmaf(tt, w0.y, acc0.y);
                acc0.z = fmaf(tt, w0.z, acc0.z);
                acc0.w = fmaf(tt, w0.w, acc0.w);
                acc1.x = fmaf(tt, w1.x, acc1.x);
                acc1.y = fmaf(tt, w1.y, acc1.y);
                acc1.z = fmaf(tt, w1.z, acc1.z);
                acc1.w = fmaf(tt, w1.w, acc1.w);
            }
        }
    }

    __syncwarp(mask);                              // all group reads of aggF done
    aggp[q] = make_float4(0.f, 0.f, 0.f, 0.f);     // restore zeros (chunks 0..3)
    if (q == 0) aggp[4] = make_float4(0.f, 0.f, 0.f, 0.f);   // chunk 4

    float4* outp = (float4*)&g_bufA[(size_t)i * 32];
    float4* zp   = (float4*)&g_bufB[(size_t)i * 32];
    outp[2 * q]     = make_float4(fmaxf(acc0.x, 0.f), fmaxf(acc0.y, 0.f),
                                  fmaxf(acc0.z, 0.f), fmaxf(acc0.w, 0.f));
    outp[2 * q + 1] = make_float4(fmaxf(acc1.x, 0.f), fmaxf(acc1.y, 0.f),
                                  fmaxf(acc1.z, 0.f), fmaxf(acc1.w, 0.f));
    zp[2 * q]     = make_float4(0.f, 0.f, 0.f, 0.f);   // pre-zero layer-2 agg
    zp[2 * q + 1] = make_float4(0.f, 0.f, 0.f, 0.f);
}

// ---------------------------------------------------------------------------
// Scatter layer 2: 8 threads per edge over 32-wide h1 (RED lane floor).
__global__ void scatter2_kernel(const int* __restrict__ ei, const float* __restrict__ ew, int E) {
    int t = blockIdx.x * blockDim.x + threadIdx.x;
    int e = t >> 3;
    int q = t & 7;
    if (e >= E) return;
    int r = ei[e];
    int c = ei[E + e];
    float nrm = g_dinv[r] * ew[e] * g_dinv[c];
    float4 v = ((const float4*)g_bufA)[(size_t)r * 8 + q];
    float vx = v.x * nrm, vy = v.y * nrm, vz = v.z * nrm, vw = v.w * nrm;
    float4* dst = ((float4*)g_bufB) + (size_t)c * 8 + q;
    asm volatile("red.global.add.v4.f32 [%0], {%1,%2,%3,%4};"
                 :: "l"(dst), "f"(vx), "f"(vy), "f"(vz), "f"(vw)
                 : "memory");
}

// ---------------------------------------------------------------------------
// Final, 2 threads per node (thread p -> h2 outputs 16p..16p+15):
// u = aggB + dinv^2*h1_self; h2 = relu(u@W2 + b2); out = h2@Wfc + bfc.
// Partner partial sums combined via shfl_xor; bufB zero-restored post-sync.
__global__ void final_kernel(const float* __restrict__ W2, const float* __restrict__ b2,
                             const float* __restrict__ Wfc, const float* __restrict__ bfc,
                             float* __restrict__ out, int n) {
    __shared__ float4 sW2[256];  // [32][32] as float4
    __shared__ float4 sb2[8];
    __shared__ float  sWfc[32];
    __shared__ float  sbfc;
    for (int j = threadIdx.x; j < 256; j += blockDim.x) sW2[j] = ((const float4*)W2)[j];
    if (threadIdx.x < 8)  sb2[threadIdx.x] = ((const float4*)b2)[threadIdx.x];
    if (threadIdx.x < 32) sWfc[threadIdx.x] = Wfc[threadIdx.x];
    if (threadIdx.x == 0) sbfc = bfc[0];
    __syncthreads();

    int t = blockIdx.x * blockDim.x + threadIdx.x;
    int i = t >> 1;
    int p = t & 1;
    bool valid = (i < n);
    unsigned mask = __ballot_sync(0xffffffffu, valid);
    if (!valid) return;

    float d = g_dinv[i];
    float s = d * d;
    float4*       aggp = (float4*)&g_bufB[(size_t)i * 32];
    const float4* hp   = (const float4*)&g_bufA[(size_t)i * 32];

    float4 acc[4];
#pragma unroll
    for (int k = 0; k < 4; k++) acc[k] = sb2[4 * p + k];

#pragma unroll
    for (int c4 = 0; c4 < 8; c4++) {
        float4 a = aggp[c4];
        float4 h = hp[c4];
        float uv[4] = { fmaf(s, h.x, a.x), fmaf(s, h.y, a.y),
                        fmaf(s, h.z, a.z), fmaf(s, h.w, a.w) };
#pragma unroll
        for (int j = 0; j < 4; j++) {
            int m = c4 * 4 + j;
            float u = uv[j];
#pragma unroll
            for (int k = 0; k < 4; k++) {
                float4 w = sW2[m * 8 + 4 * p + k];
                acc[k].x = fmaf(u, w.x, acc[k].x);
                acc[k].y = fmaf(u, w.y, acc[k].y);
                acc[k].z = fmaf(u, w.z, acc[k].z);
                acc[k].w = fmaf(u, w.w, acc[k].w);
            }
        }
    }

    __syncwarp(mask);                                  // partner reads done
#pragma unroll
    for (int k = 0; k < 4; k++)                        // restore zeros (4 chunks each)
        aggp[4 * p + k] = make_float4(0.f, 0.f, 0.f, 0.f);

    float o = (p == 0) ? sbfc : 0.f;
#pragma unroll
    for (int k = 0; k < 4; k++) {
        int base = 16 * p + 4 * k;
        o = fmaf(fmaxf(acc[k].x, 0.f), sWfc[base + 0], o);
        o = fmaf(fmaxf(acc[k].y, 0.f), sWfc[base + 1], o);
        o = fmaf(fmaxf(acc[k].z, 0.f), sWfc[base + 2], o);
        o = fmaf(fmaxf(acc[k].w, 0.f), sWfc[base + 3], o);
    }
    o += __shfl_xor_sync(mask, o, 1);
    if (p == 0) out[i] = o;
}

// ---------------------------------------------------------------------------
extern "C" void kernel_launch(void* const* d_in, const int* in_sizes, int n_in,
                              void* d_out, int out_size) {
    const float* x   = (const float*)d_in[0];
    const float* c   = (const float*)d_in[1];
    const int*   ei  = (const int*)d_in[2];
    const float* ew  = (const float*)d_in[3];
    const float* We1 = (const float*)d_in[4];
    const float* be1 = (const float*)d_in[5];
    const float* We2 = (const float*)d_in[6];
    const float* be2 = (const float*)d_in[7];
    const float* W1  = (const float*)d_in[8];
    const float* b1  = (const float*)d_in[9];
    const float* W2  = (const float*)d_in[10];
    const float* b2  = (const float*)d_in[11];
    const float* Wfc = (const float*)d_in[12];
    const float* bfc = (const float*)d_in[13];

    int n = in_sizes[1] / 2;   // c is [N, 2]
    int E = in_sizes[3];       // ew is [E]
    const int TB = 256;

    int E4 = E / 4;
    deg_kernel  <<<(E4 + TB - 1) / TB, TB>>>(ei + E, ew, E4);
    embed_kernel<<<(n + TB - 1) / TB, TB>>>(x, c, We1, be1, We2, be2, n);
    scatter1_kernel<<<((size_t)E * 5 + TB - 1) / TB, TB>>>(ei, ew, E);   // 20-wide feat
    mid_kernel  <<<((size_t)n * 4 + TB - 1) / TB, TB>>>(W1, b1, n);      // 4 thr/node
    scatter2_kernel<<<((size_t)E * 8 + TB - 1) / TB, TB>>>(ei, ew, E);   // 32-wide h1
    final_kernel<<<((size_t)n * 2 + TB - 1) / TB, TB>>>(W2, b2, Wfc, bfc, (float*)d_out, n);
}